// round 8
// baseline (speedup 1.0000x reference)
#include <cuda_runtime.h>
#include <cuda_fp16.h>
#include <cstdint>
#include <cstddef>

// Problem dims
#define MDIM 8192   // B*S
#define NDIM 4096   // OUT
#define KDIM 4096   // IN
#define RANK 32
#define NGROUPS 32  // IN/128

// GEMM tiling (legacy mma.sync path: tcgen05 not available through compute_103 PTX)
#define BM 128
#define BN 256
#define BK 64
#define NSTAGES 3
#define KT (KDIM / BK)  // 64

#define A_STAGE_BYTES (BM * 128)                     // 16 KB (128 rows x 128B)
#define B_STAGE_BYTES (BN * 128)                     // 32 KB
#define STAGE_BYTES (A_STAGE_BYTES + B_STAGE_BYTES)  // 48 KB
#define SMEM_BYTES (NSTAGES * STAGE_BYTES)           // 144 KB

// Scratch (allocation-free rule: __device__ globals)
__device__ __half g_Xh[(size_t)MDIM * KDIM];  // 64 MB
__device__ __half g_Wh[(size_t)NDIM * KDIM];  // 32 MB

// ---------------------------------------------------------------------------
// helpers
// ---------------------------------------------------------------------------
__device__ __forceinline__ uint32_t smem_u32(const void* p) {
    uint32_t a;
    asm("{ .reg .u64 t; cvta.to.shared.u64 t, %1; cvt.u32.u64 %0, t; }"
        : "=r"(a) : "l"(p));
    return a;
}

__device__ __forceinline__ void cpa16(uint32_t s, const void* g) {
    asm volatile("cp.async.cg.shared.global [%0], [%1], 16;" :: "r"(s), "l"(g));
}

__device__ __forceinline__ void ldsm_x4(uint32_t& r0, uint32_t& r1, uint32_t& r2,
                                        uint32_t& r3, uint32_t addr) {
    asm volatile("ldmatrix.sync.aligned.m8n8.x4.shared.b16 {%0,%1,%2,%3}, [%4];"
                 : "=r"(r0), "=r"(r1), "=r"(r2), "=r"(r3) : "r"(addr));
}

__device__ __forceinline__ void mma16816(float* c, const uint32_t* a,
                                         const uint32_t* b) {
    asm volatile(
        "mma.sync.aligned.m16n8k16.row.col.f32.f16.f16.f32 "
        "{%0,%1,%2,%3}, {%4,%5,%6,%7}, {%8,%9}, {%0,%1,%2,%3};"
        : "+f"(c[0]), "+f"(c[1]), "+f"(c[2]), "+f"(c[3])
        : "r"(a[0]), "r"(a[1]), "r"(a[2]), "r"(a[3]), "r"(b[0]), "r"(b[1]));
}

// ---------------------------------------------------------------------------
// P2: x (fp32) -> g_Xh (fp16)
// ---------------------------------------------------------------------------
__global__ void cast_x_kernel(const float* __restrict__ x) {
    size_t idx = (size_t)blockIdx.x * 256 + threadIdx.x;  // one float4 each
    float4 f = reinterpret_cast<const float4*>(x)[idx];
    __half2* o = reinterpret_cast<__half2*>(g_Xh);
    o[2 * idx + 0] = __floats2half2_rn(f.x, f.y);
    o[2 * idx + 1] = __floats2half2_rn(f.z, f.w);
}

// ---------------------------------------------------------------------------
// P1: g_Wh[o,i] = fp16( (q[o,i]-8)*scales[o,i/128] + sum_k U[o,k]*V[k,i] )
// ---------------------------------------------------------------------------
__global__ void build_w_kernel(const int* __restrict__ q,
                               const float* __restrict__ scales,
                               const float* __restrict__ U,
                               const float* __restrict__ V) {
    __shared__ float Vs[RANK * 256];
    __shared__ float Us[16 * RANK];
    const int bx = blockIdx.x;      // 4096 blocks
    const int ot = bx >> 4;         // 0..255
    const int itile = bx & 15;      // 0..15
    const int o0 = ot * 16;
    const int i0 = itile * 256;
    const int tid = threadIdx.x;

#pragma unroll
    for (int k = 0; k < RANK; k++)
        Vs[k * 256 + tid] = V[(size_t)k * KDIM + i0 + tid];
    Us[tid]       = U[(size_t)o0 * RANK + tid];
    Us[tid + 256] = U[(size_t)o0 * RANK + 256 + tid];
    __syncthreads();

    float v[RANK];
#pragma unroll
    for (int k = 0; k < RANK; k++) v[k] = Vs[k * 256 + tid];

    const int i = i0 + tid;
#pragma unroll 4
    for (int oo = 0; oo < 16; oo++) {
        const int o = o0 + oo;
        float acc = 0.f;
#pragma unroll
        for (int k = 0; k < RANK; k++) acc = fmaf(Us[oo * RANK + k], v[k], acc);
        const float w =
            (float)(q[(size_t)o * KDIM + i] - 8) * scales[o * NGROUPS + (i >> 7)] + acc;
        g_Wh[(size_t)o * KDIM + i] = __float2half_rn(w);
    }
}

// ---------------------------------------------------------------------------
// GEMM: out[m,n] = sum_k Xh[m,k]*Wh[n,k] + bias[n]
// 128x256x64 CTA tile, 1 CTA/SM, 8 warps (2m x 4n), warp tile 64x64,
// 3-stage cp.async, mma.sync.m16n8k16 fp32 acc, SW128 swizzle + ldmatrix.
// ---------------------------------------------------------------------------
__device__ __forceinline__ void load_stage(uint32_t sb, int slot, int kb,
                                           int m0, int n0, int tid) {
    const uint32_t sA = sb + slot * STAGE_BYTES;
    const uint32_t sB = sA + A_STAGE_BYTES;
    const int k0 = kb * BK;
#pragma unroll
    for (int i = 0; i < 4; i++) {  // A: 128 rows x 128B = 1024 x 16B chunks
        const int idx = tid + (i << 8);
        const int r = idx >> 3, c = idx & 7;
        const void* g = g_Xh + ((size_t)(m0 + r) * KDIM + k0 + c * 8);
        const uint32_t so = (uint32_t)(r * 128 + c * 16);
        cpa16(sA + (so ^ ((uint32_t)(r & 7) << 4)), g);
    }
#pragma unroll
    for (int i = 0; i < 8; i++) {  // B: 256 rows x 128B = 2048 x 16B chunks
        const int idx = tid + (i << 8);
        const int r = idx >> 3, c = idx & 7;
        const void* g = g_Wh + ((size_t)(n0 + r) * KDIM + k0 + c * 8);
        const uint32_t so = (uint32_t)(r * 128 + c * 16);
        cpa16(sB + (so ^ ((uint32_t)(r & 7) << 4)), g);
    }
}

// swizzled SMEM byte offset for (row, half-col ch) within a 128B-row tile
__device__ __forceinline__ uint32_t swz(int row, int ch) {
    const uint32_t so = (uint32_t)(row * 128 + ch * 2);
    return so ^ ((uint32_t)(row & 7) << 4);
}

__global__ void __launch_bounds__(256, 1)
gemm_kernel(const float* __restrict__ bias, float* __restrict__ out) {
    extern __shared__ char smem_raw[];
    const uint32_t sb = smem_u32(smem_raw);
    const int tid = threadIdx.x;
    const int wid = tid >> 5;
    const int lane = tid & 31;
    const int wm = wid >> 2;   // 0..1  -> 64-row slice
    const int wn = wid & 3;    // 0..3  -> 64-col slice

    // supertiled rasterization: 8 groups of 128 CTAs cover 16 mt x 8 nt
    const int bid = blockIdx.x;          // 0..1023
    const int g = bid >> 7;              // 0..7
    const int rem = bid & 127;
    const int mt = (g & 3) * 16 + (rem & 15);   // 0..63
    const int nt = (g >> 2) * 8 + (rem >> 4);   // 0..15
    const int m0 = mt * BM;
    const int n0 = nt * BN;

    float acc[4][8][4];
#pragma unroll
    for (int i = 0; i < 4; i++)
#pragma unroll
        for (int j = 0; j < 8; j++)
#pragma unroll
            for (int r = 0; r < 4; r++) acc[i][j][r] = 0.f;

    // prologue: stages 0..NSTAGES-2
#pragma unroll
    for (int s = 0; s < NSTAGES - 1; s++) {
        load_stage(sb, s, s, m0, n0, tid);
        asm volatile("cp.async.commit_group;" ::: "memory");
    }

    for (int it = 0; it < KT; ++it) {
        asm volatile("cp.async.wait_group 1;" ::: "memory");
        __syncthreads();

        // issue next stage load (overwrites slot computed at it-1)
        const int nk = it + NSTAGES - 1;
        if (nk < KT) load_stage(sb, nk % NSTAGES, nk, m0, n0, tid);
        asm volatile("cp.async.commit_group;" ::: "memory");

        // compute on slot it%NSTAGES
        const uint32_t sA = sb + (it % NSTAGES) * STAGE_BYTES;
        const uint32_t sBt = sA + A_STAGE_BYTES;
#pragma unroll
        for (int ks = 0; ks < 4; ks++) {
            uint32_t a[4][4], b[8][2];
            const int ch = ks * 16 + (lane >> 4) * 8;
            // A: four 16x16 fragments (rows wm*64 + mi*16 + ..)
#pragma unroll
            for (int mi = 0; mi < 4; mi++) {
                const int row = wm * 64 + mi * 16 + (lane & 15);
                ldsm_x4(a[mi][0], a[mi][1], a[mi][2], a[mi][3], sA + swz(row, ch));
            }
            // B: four x4 loads, each covering 16 n-rows -> two n-frags
#pragma unroll
            for (int nf4 = 0; nf4 < 4; nf4++) {
                const int row = wn * 64 + nf4 * 16 + (lane & 15);
                uint32_t r0, r1, r2, r3;
                ldsm_x4(r0, r1, r2, r3, sBt + swz(row, ch));
                b[nf4 * 2 + 0][0] = r0;
                b[nf4 * 2 + 1][0] = r1;
                b[nf4 * 2 + 0][1] = r2;
                b[nf4 * 2 + 1][1] = r3;
            }
#pragma unroll
            for (int mi = 0; mi < 4; mi++)
#pragma unroll
                for (int nf = 0; nf < 8; nf++)
                    mma16816(acc[mi][nf], a[mi], b[nf]);
        }
    }

    // epilogue: c frag mapping: row = base + lane/4 (+8), col = nf*8 + (lane%4)*2
    const int rbase = m0 + wm * 64 + (lane >> 2);
    const int cbase = n0 + wn * 64 + (lane & 3) * 2;
#pragma unroll
    for (int mi = 0; mi < 4; mi++) {
#pragma unroll
        for (int nf = 0; nf < 8; nf++) {
            const int col = cbase + nf * 8;
            const float2 b2 = *reinterpret_cast<const float2*>(bias + col);
            const int r0 = rbase + mi * 16;
            float2 v0 = {acc[mi][nf][0] + b2.x, acc[mi][nf][1] + b2.y};
            float2 v1 = {acc[mi][nf][2] + b2.x, acc[mi][nf][3] + b2.y};
            *reinterpret_cast<float2*>(out + (size_t)r0 * NDIM + col) = v0;
            *reinterpret_cast<float2*>(out + (size_t)(r0 + 8) * NDIM + col) = v1;
        }
    }
}

// ---------------------------------------------------------------------------
// launch
// ---------------------------------------------------------------------------
extern "C" void kernel_launch(void* const* d_in, const int* in_sizes, int n_in,
                              void* d_out, int out_size) {
    const float* x     = (const float*)d_in[0];
    const int*   q     = (const int*)d_in[1];
    const float* sc    = (const float*)d_in[2];
    const float* U     = (const float*)d_in[3];
    const float* V     = (const float*)d_in[4];
    const float* bias  = (const float*)d_in[5];
    float* out = (float*)d_out;

    cast_x_kernel<<<(MDIM * (KDIM / 4)) / 256, 256>>>(x);
    build_w_kernel<<<(NDIM / 16) * (KDIM / 256), 256>>>(q, sc, U, V);

    cudaFuncSetAttribute(gemm_kernel, cudaFuncAttributeMaxDynamicSharedMemorySize,
                         SMEM_BYTES);
    gemm_kernel<<<(MDIM / BM) * (NDIM / BN), 256, SMEM_BYTES>>>(bias, out);
}

// round 9
// speedup vs baseline: 1.1166x; 1.1166x over previous
#include <cuda_runtime.h>
#include <cuda_fp16.h>
#include <cstdint>
#include <cstddef>

// Problem dims
#define MDIM 8192   // B*S
#define NDIM 4096   // OUT
#define KDIM 4096   // IN
#define RANK 32
#define NGROUPS 32  // IN/128

// GEMM tiling (legacy mma.sync path: tcgen05 not available through compute_103 PTX)
#define BM 128
#define BN 128
#define BK 64
#define NSTAGES 3
#define KT (KDIM / BK)  // 64

#define A_STAGE_BYTES (BM * 128)                     // 16 KB (128 rows x 128B)
#define B_STAGE_BYTES (BN * 128)                     // 16 KB
#define STAGE_BYTES (A_STAGE_BYTES + B_STAGE_BYTES)  // 32 KB
#define SMEM_BYTES (NSTAGES * STAGE_BYTES)           // 96 KB

// Scratch (allocation-free rule: __device__ globals)
__device__ __half g_Xh[(size_t)MDIM * KDIM];  // 64 MB
__device__ __half g_Wh[(size_t)NDIM * KDIM];  // 32 MB

// ---------------------------------------------------------------------------
// helpers
// ---------------------------------------------------------------------------
__device__ __forceinline__ uint32_t smem_u32(const void* p) {
    uint32_t a;
    asm("{ .reg .u64 t; cvta.to.shared.u64 t, %1; cvt.u32.u64 %0, t; }"
        : "=r"(a) : "l"(p));
    return a;
}

__device__ __forceinline__ void cpa16(uint32_t s, const void* g) {
    asm volatile("cp.async.cg.shared.global [%0], [%1], 16;" :: "r"(s), "l"(g));
}

__device__ __forceinline__ void ldsm_x4(uint32_t& r0, uint32_t& r1, uint32_t& r2,
                                        uint32_t& r3, uint32_t addr) {
    asm volatile("ldmatrix.sync.aligned.m8n8.x4.shared.b16 {%0,%1,%2,%3}, [%4];"
                 : "=r"(r0), "=r"(r1), "=r"(r2), "=r"(r3) : "r"(addr));
}

__device__ __forceinline__ void mma16816(float* c, const uint32_t* a,
                                         const uint32_t* b) {
    asm volatile(
        "mma.sync.aligned.m16n8k16.row.col.f32.f16.f16.f32 "
        "{%0,%1,%2,%3}, {%4,%5,%6,%7}, {%8,%9}, {%0,%1,%2,%3};"
        : "+f"(c[0]), "+f"(c[1]), "+f"(c[2]), "+f"(c[3])
        : "r"(a[0]), "r"(a[1]), "r"(a[2]), "r"(a[3]), "r"(b[0]), "r"(b[1]));
}

// ---------------------------------------------------------------------------
// P2: x (fp32) -> g_Xh (fp16)
// ---------------------------------------------------------------------------
__global__ void cast_x_kernel(const float* __restrict__ x) {
    size_t idx = (size_t)blockIdx.x * 256 + threadIdx.x;  // one float4 each
    float4 f = reinterpret_cast<const float4*>(x)[idx];
    __half2* o = reinterpret_cast<__half2*>(g_Xh);
    o[2 * idx + 0] = __floats2half2_rn(f.x, f.y);
    o[2 * idx + 1] = __floats2half2_rn(f.z, f.w);
}

// ---------------------------------------------------------------------------
// P1: g_Wh[o,i] = fp16( (q[o,i]-8)*scales[o,i/128] + sum_k U[o,k]*V[k,i] )
// ---------------------------------------------------------------------------
__global__ void build_w_kernel(const int* __restrict__ q,
                               const float* __restrict__ scales,
                               const float* __restrict__ U,
                               const float* __restrict__ V) {
    __shared__ float Vs[RANK * 256];
    __shared__ float Us[16 * RANK];
    const int bx = blockIdx.x;      // 4096 blocks
    const int ot = bx >> 4;         // 0..255
    const int itile = bx & 15;      // 0..15
    const int o0 = ot * 16;
    const int i0 = itile * 256;
    const int tid = threadIdx.x;

#pragma unroll
    for (int k = 0; k < RANK; k++)
        Vs[k * 256 + tid] = V[(size_t)k * KDIM + i0 + tid];
    Us[tid]       = U[(size_t)o0 * RANK + tid];
    Us[tid + 256] = U[(size_t)o0 * RANK + 256 + tid];
    __syncthreads();

    float v[RANK];
#pragma unroll
    for (int k = 0; k < RANK; k++) v[k] = Vs[k * 256 + tid];

    const int i = i0 + tid;
#pragma unroll 4
    for (int oo = 0; oo < 16; oo++) {
        const int o = o0 + oo;
        float acc = 0.f;
#pragma unroll
        for (int k = 0; k < RANK; k++) acc = fmaf(Us[oo * RANK + k], v[k], acc);
        const float w =
            (float)(q[(size_t)o * KDIM + i] - 8) * scales[o * NGROUPS + (i >> 7)] + acc;
        g_Wh[(size_t)o * KDIM + i] = __float2half_rn(w);
    }
}

// ---------------------------------------------------------------------------
// GEMM: out[m,n] = sum_k Xh[m,k]*Wh[n,k] + bias[n]
// 128x128x64 tiles, 3-stage cp.async, 8 warps (4m x 2n), warp tile 32x64,
// 2 CTAs/SM. cp.async for the next stage is issued AFTER the first ks chunk
// so MMAs start immediately post-barrier and LSU issue overlaps tensor work.
// ---------------------------------------------------------------------------
__device__ __forceinline__ void load_stage(uint32_t sb, int slot, int kb,
                                           int m0, int n0, int tid) {
    const uint32_t sA = sb + slot * STAGE_BYTES;
    const uint32_t sB = sA + A_STAGE_BYTES;
    const int k0 = kb * BK;
#pragma unroll
    for (int i = 0; i < 4; i++) {  // A: 128 rows x 128B = 1024 x 16B chunks
        const int idx = tid + (i << 8);
        const int r = idx >> 3, c = idx & 7;
        const void* g = g_Xh + ((size_t)(m0 + r) * KDIM + k0 + c * 8);
        const uint32_t so = (uint32_t)(r * 128 + c * 16);
        cpa16(sA + (so ^ ((uint32_t)(r & 7) << 4)), g);
    }
#pragma unroll
    for (int i = 0; i < 4; i++) {  // B: 128 rows x 128B
        const int idx = tid + (i << 8);
        const int r = idx >> 3, c = idx & 7;
        const void* g = g_Wh + ((size_t)(n0 + r) * KDIM + k0 + c * 8);
        const uint32_t so = (uint32_t)(r * 128 + c * 16);
        cpa16(sB + (so ^ ((uint32_t)(r & 7) << 4)), g);
    }
}

// swizzled SMEM byte offset for (row, half-col ch) within a 128B-row tile
__device__ __forceinline__ uint32_t swz(int row, int ch) {
    const uint32_t so = (uint32_t)(row * 128 + ch * 2);
    return so ^ ((uint32_t)(row & 7) << 4);
}

// one k16 chunk of the warp tile: 6 LDSM.x4 + 16 MMA
__device__ __forceinline__ void compute_ks(uint32_t sA, uint32_t sBt, int ks,
                                           int wm, int wn, int lane,
                                           float (*acc)[4] /* [16][4] as [mi*8+nf] */) {
    uint32_t a[2][4], b[8][2];
    const int ch = ks * 16 + (lane >> 4) * 8;
#pragma unroll
    for (int mi = 0; mi < 2; mi++) {
        const int row = wm * 32 + mi * 16 + (lane & 15);
        ldsm_x4(a[mi][0], a[mi][1], a[mi][2], a[mi][3], sA + swz(row, ch));
    }
#pragma unroll
    for (int nf4 = 0; nf4 < 4; nf4++) {
        const int row = wn * 64 + nf4 * 16 + (lane & 15);
        uint32_t r0, r1, r2, r3;
        ldsm_x4(r0, r1, r2, r3, sBt + swz(row, ch));
        b[nf4 * 2 + 0][0] = r0;
        b[nf4 * 2 + 1][0] = r1;
        b[nf4 * 2 + 0][1] = r2;
        b[nf4 * 2 + 1][1] = r3;
    }
#pragma unroll
    for (int mi = 0; mi < 2; mi++)
#pragma unroll
        for (int nf = 0; nf < 8; nf++)
            mma16816(acc[mi * 8 + nf], a[mi], b[nf]);
}

__global__ void __launch_bounds__(256, 2)
gemm_kernel(const float* __restrict__ bias, float* __restrict__ out) {
    extern __shared__ char smem_raw[];
    const uint32_t sb = smem_u32(smem_raw);
    const int tid = threadIdx.x;
    const int wid = tid >> 5;
    const int lane = tid & 31;
    const int wm = wid >> 1;   // 0..3  -> 32-row slice
    const int wn = wid & 1;    // 0..1  -> 64-col slice

    // supertiled rasterization: 8 groups of 256 CTAs cover 16 mt x 16 nt
    const int bid = blockIdx.x;          // 0..2047
    const int g = bid >> 8;
    const int rem = bid & 255;
    const int mt = (g & 3) * 16 + (rem & 15);    // 0..63
    const int nt = (g >> 2) * 16 + (rem >> 4);   // 0..31
    const int m0 = mt * BM;
    const int n0 = nt * BN;

    float acc[16][4];
#pragma unroll
    for (int j = 0; j < 16; j++)
#pragma unroll
        for (int r = 0; r < 4; r++) acc[j][r] = 0.f;

    // prologue: stages 0..NSTAGES-2
#pragma unroll
    for (int s = 0; s < NSTAGES - 1; s++) {
        load_stage(sb, s, s, m0, n0, tid);
        asm volatile("cp.async.commit_group;" ::: "memory");
    }

    for (int it = 0; it < KT; ++it) {
        asm volatile("cp.async.wait_group 1;" ::: "memory");
        __syncthreads();

        const uint32_t sA = sb + (it % NSTAGES) * STAGE_BYTES;
        const uint32_t sBt = sA + A_STAGE_BYTES;

        // ks=0 first: LDSMs hit the shared pipe immediately after the barrier,
        // MMAs start ~100 cyc earlier than with loads-first ordering
        compute_ks(sA, sBt, 0, wm, wn, lane, acc);

        // issue next stage while ks=0 MMAs occupy the tensor pipe
        const int nk = it + NSTAGES - 1;
        if (nk < KT) load_stage(sb, nk % NSTAGES, nk, m0, n0, tid);
        asm volatile("cp.async.commit_group;" ::: "memory");

        compute_ks(sA, sBt, 1, wm, wn, lane, acc);
        compute_ks(sA, sBt, 2, wm, wn, lane, acc);
        compute_ks(sA, sBt, 3, wm, wn, lane, acc);
    }

    // epilogue: c frag mapping: row = base + lane/4 (+8), col = nf*8 + (lane%4)*2
    const int rbase = m0 + wm * 32 + (lane >> 2);
    const int cbase = n0 + wn * 64 + (lane & 3) * 2;
#pragma unroll
    for (int mi = 0; mi < 2; mi++) {
#pragma unroll
        for (int nf = 0; nf < 8; nf++) {
            const int col = cbase + nf * 8;
            const float2 b2 = *reinterpret_cast<const float2*>(bias + col);
            const int r0 = rbase + mi * 16;
            float2 v0 = {acc[mi * 8 + nf][0] + b2.x, acc[mi * 8 + nf][1] + b2.y};
            float2 v1 = {acc[mi * 8 + nf][2] + b2.x, acc[mi * 8 + nf][3] + b2.y};
            *reinterpret_cast<float2*>(out + (size_t)r0 * NDIM + col) = v0;
            *reinterpret_cast<float2*>(out + (size_t)(r0 + 8) * NDIM + col) = v1;
        }
    }
}

// ---------------------------------------------------------------------------
// launch
// ---------------------------------------------------------------------------
extern "C" void kernel_launch(void* const* d_in, const int* in_sizes, int n_in,
                              void* d_out, int out_size) {
    const float* x     = (const float*)d_in[0];
    const int*   q     = (const int*)d_in[1];
    const float* sc    = (const float*)d_in[2];
    const float* U     = (const float*)d_in[3];
    const float* V     = (const float*)d_in[4];
    const float* bias  = (const float*)d_in[5];
    float* out = (float*)d_out;

    cast_x_kernel<<<(MDIM * (KDIM / 4)) / 256, 256>>>(x);
    build_w_kernel<<<(NDIM / 16) * (KDIM / 256), 256>>>(q, sc, U, V);

    cudaFuncSetAttribute(gemm_kernel, cudaFuncAttributeMaxDynamicSharedMemorySize,
                         SMEM_BYTES);
    gemm_kernel<<<(MDIM / BM) * (NDIM / BN), 256, SMEM_BYTES>>>(bias, out);
}